// round 2
// baseline (speedup 1.0000x reference)
#include <cuda_runtime.h>
#include <cuda_bf16.h>

#define BATCH   16
#define CDIM    256
#define NPIX    4096      // 64*64
#define O3      768       // 3 * HEADS * DH
#define HEADS   4
#define DH      64
#define NSPLIT  8

// ---- scratch (device globals: allowed; no runtime allocation) ----
__device__ float g_qkv [BATCH * O3 * NPIX];                    // [b][o][n]  (201 MB)
__device__ float g_ctxp[BATCH * HEADS * NSPLIT * DH * DH];     // partial contexts (8 MB)
__device__ float g_ctx [BATCH * HEADS * DH * DH];              // [b][h][d][e] (1 MB)
__device__ float g_att [BATCH * CDIM * NPIX];                  // attention out (64 MB)

// ============================================================================
// Generic tiled SGEMM: C[b] = A[M,K] @ B[b][K,NPIX]   (A shared across batch)
// 128x128 tile, TK=8, 256 threads, 8x8 microtile.
// EPI=1: C = gamma[m]*(acc + bias[m]) + xres[b][m][n]
// ============================================================================
template<int EPI>
__global__ __launch_bounds__(256)
void gemm_tn(const float* __restrict__ A,
             const float* __restrict__ Bm,
             float* __restrict__ Cm,
             int K,
             long strideB, long strideC,
             const float* __restrict__ bias,
             const float* __restrict__ gamma,
             const float* __restrict__ xres)
{
    __shared__ float As[8][128];
    __shared__ float Bs[8][128];

    const int bz = blockIdx.z;
    const float* Bp = Bm + (size_t)bz * strideB;
    float*       Cp = Cm + (size_t)bz * strideC;

    const int m0 = blockIdx.y * 128;
    const int n0 = blockIdx.x * 128;
    const int t  = threadIdx.x;
    const int ty = t >> 4, tx = t & 15;

    float acc[8][8];
    #pragma unroll
    for (int i = 0; i < 8; i++)
        #pragma unroll
        for (int j = 0; j < 8; j++) acc[i][j] = 0.f;

    const int arow = t >> 1;          // 0..127
    const int af   = (t & 1) * 4;     // 0 or 4
    const int bkk  = t >> 5;          // 0..7
    const int bnn  = (t & 31) * 4;    // 0..124

    for (int k0 = 0; k0 < K; k0 += 8) {
        float4 av = *(const float4*)(A + (size_t)(m0 + arow) * K + k0 + af);
        As[af + 0][arow] = av.x;
        As[af + 1][arow] = av.y;
        As[af + 2][arow] = av.z;
        As[af + 3][arow] = av.w;
        *(float4*)&Bs[bkk][bnn] =
            *(const float4*)(Bp + (size_t)(k0 + bkk) * NPIX + n0 + bnn);
        __syncthreads();

        #pragma unroll
        for (int kk = 0; kk < 8; kk++) {
            float4 a0 = *(float4*)&As[kk][ty * 8];
            float4 a1 = *(float4*)&As[kk][ty * 8 + 4];
            float4 b0 = *(float4*)&Bs[kk][tx * 8];
            float4 b1 = *(float4*)&Bs[kk][tx * 8 + 4];
            float a[8] = {a0.x, a0.y, a0.z, a0.w, a1.x, a1.y, a1.z, a1.w};
            float b[8] = {b0.x, b0.y, b0.z, b0.w, b1.x, b1.y, b1.z, b1.w};
            #pragma unroll
            for (int i = 0; i < 8; i++)
                #pragma unroll
                for (int j = 0; j < 8; j++)
                    acc[i][j] = fmaf(a[i], b[j], acc[i][j]);
        }
        __syncthreads();
    }

    const float* xp = EPI ? (xres + (size_t)bz * strideC) : nullptr;
    #pragma unroll
    for (int i = 0; i < 8; i++) {
        int m = m0 + ty * 8 + i;
        size_t off = (size_t)m * NPIX + n0 + tx * 8;
        if (EPI) {
            float g = gamma[m], bo = bias[m];
            float4 r0 = *(const float4*)(xp + off);
            float4 r1 = *(const float4*)(xp + off + 4);
            float4 o0, o1;
            o0.x = fmaf(g, acc[i][0] + bo, r0.x);
            o0.y = fmaf(g, acc[i][1] + bo, r0.y);
            o0.z = fmaf(g, acc[i][2] + bo, r0.z);
            o0.w = fmaf(g, acc[i][3] + bo, r0.w);
            o1.x = fmaf(g, acc[i][4] + bo, r1.x);
            o1.y = fmaf(g, acc[i][5] + bo, r1.y);
            o1.z = fmaf(g, acc[i][6] + bo, r1.z);
            o1.w = fmaf(g, acc[i][7] + bo, r1.w);
            *(float4*)(Cp + off)     = o0;
            *(float4*)(Cp + off + 4) = o1;
        } else {
            float4 o0 = {acc[i][0], acc[i][1], acc[i][2], acc[i][3]};
            float4 o1 = {acc[i][4], acc[i][5], acc[i][6], acc[i][7]};
            *(float4*)(Cp + off)     = o0;
            *(float4*)(Cp + off + 4) = o1;
        }
    }
}

// ============================================================================
// Softmax over n (4096) for the K rows of qkv (in place).
// One block (256 threads) per row; 16 elements per thread held in registers.
// ============================================================================
__global__ __launch_bounds__(256)
void softmax_k(float* __restrict__ qkv)
{
    int r  = blockIdx.x;            // 0 .. BATCH*256-1
    int b  = r >> 8;
    int hd = r & 255;
    float* row = qkv + ((size_t)b * O3 + 256 + hd) * (size_t)NPIX;

    int t = threadIdx.x;
    float4 v[4];
    float mx = -3.4e38f;
    #pragma unroll
    for (int i = 0; i < 4; i++) {
        v[i] = ((const float4*)row)[t + i * 256];
        mx = fmaxf(mx, fmaxf(fmaxf(v[i].x, v[i].y), fmaxf(v[i].z, v[i].w)));
    }

    __shared__ float sred[8];
    int lane = t & 31, w = t >> 5;

    #pragma unroll
    for (int o = 16; o; o >>= 1) mx = fmaxf(mx, __shfl_xor_sync(0xffffffffu, mx, o));
    if (lane == 0) sred[w] = mx;
    __syncthreads();
    if (t < 8) {
        float m2 = sred[t];
        #pragma unroll
        for (int o = 4; o; o >>= 1) m2 = fmaxf(m2, __shfl_xor_sync(0xffu, m2, o));
        if (t == 0) sred[0] = m2;
    }
    __syncthreads();
    mx = sred[0];
    __syncthreads();

    float sum = 0.f;
    #pragma unroll
    for (int i = 0; i < 4; i++) {
        v[i].x = __expf(v[i].x - mx);
        v[i].y = __expf(v[i].y - mx);
        v[i].z = __expf(v[i].z - mx);
        v[i].w = __expf(v[i].w - mx);
        sum += v[i].x + v[i].y + v[i].z + v[i].w;
    }
    #pragma unroll
    for (int o = 16; o; o >>= 1) sum += __shfl_xor_sync(0xffffffffu, sum, o);
    if (lane == 0) sred[w] = sum;
    __syncthreads();
    if (t < 8) {
        float s2 = sred[t];
        #pragma unroll
        for (int o = 4; o; o >>= 1) s2 += __shfl_xor_sync(0xffu, s2, o);
        if (t == 0) sred[0] = s2;
    }
    __syncthreads();
    float inv = 1.0f / sred[0];

    #pragma unroll
    for (int i = 0; i < 4; i++) {
        v[i].x *= inv; v[i].y *= inv; v[i].z *= inv; v[i].w *= inv;
        ((float4*)row)[t + i * 256] = v[i];
    }
}

// ============================================================================
// context partial: ctxp[b,h,s,d,e] = sum_{n in split s} k[d,n]*v[e,n]
// grid (NSPLIT, HEADS, BATCH), 256 threads, 4x4 microtile of 64x64 output.
// ============================================================================
__global__ __launch_bounds__(256)
void ctx_partial(const float* __restrict__ qkv, float* __restrict__ ctxp)
{
    int s = blockIdx.x, h = blockIdx.y, b = blockIdx.z;
    const float* kbase = qkv + ((size_t)b * O3 + 256 + h * DH) * (size_t)NPIX;
    const float* vbase = qkv + ((size_t)b * O3 + 512 + h * DH) * (size_t)NPIX;

    __shared__ float Ks[32][68];   // [nn][d], padded
    __shared__ float Vs[32][68];

    int t  = threadIdx.x;
    int ty = t >> 4, tx = t & 15;
    int ld_d  = t >> 5;       // 0..7
    int ld_nn = t & 31;       // 0..31

    float acc[4][4];
    #pragma unroll
    for (int i = 0; i < 4; i++)
        #pragma unroll
        for (int j = 0; j < 4; j++) acc[i][j] = 0.f;

    int nbeg = s * (NPIX / NSPLIT);
    int nend = nbeg + (NPIX / NSPLIT);
    for (int n0 = nbeg; n0 < nend; n0 += 32) {
        #pragma unroll
        for (int i = 0; i < 8; i++) {
            int d = ld_d + i * 8;
            Ks[ld_nn][d] = kbase[(size_t)d * NPIX + n0 + ld_nn];
            Vs[ld_nn][d] = vbase[(size_t)d * NPIX + n0 + ld_nn];
        }
        __syncthreads();
        #pragma unroll
        for (int nn = 0; nn < 32; nn++) {
            float4 a = *(float4*)&Ks[nn][ty * 4];
            float4 v = *(float4*)&Vs[nn][tx * 4];
            float av[4] = {a.x, a.y, a.z, a.w};
            float bv[4] = {v.x, v.y, v.z, v.w};
            #pragma unroll
            for (int i = 0; i < 4; i++)
                #pragma unroll
                for (int j = 0; j < 4; j++)
                    acc[i][j] = fmaf(av[i], bv[j], acc[i][j]);
        }
        __syncthreads();
    }

    size_t base = (((size_t)(b * HEADS + h) * NSPLIT + s) * DH) * DH;
    #pragma unroll
    for (int i = 0; i < 4; i++) {
        float4 o = {acc[i][0], acc[i][1], acc[i][2], acc[i][3]};
        *(float4*)&ctxp[base + (size_t)(ty * 4 + i) * DH + tx * 4] = o;
    }
}

__global__ __launch_bounds__(256)
void ctx_reduce(const float* __restrict__ ctxp, float* __restrict__ ctx)
{
    int i  = blockIdx.x * 256 + threadIdx.x;     // 0 .. 262143
    int bh = i >> 12;
    int de = i & 4095;
    float s = 0.f;
    #pragma unroll
    for (int sp = 0; sp < NSPLIT; sp++)
        s += ctxp[((size_t)bh * NSPLIT + sp) * 4096 + de];
    ctx[i] = s;
}

// ============================================================================
// out[b, h*64+e, n] = sum_d ctx[b,h,d,e] * q[b,h,d,n]
// grid (NPIX/128, HEADS, BATCH), 256 threads, 4x8 microtile of 64x128 tile.
// ============================================================================
__global__ __launch_bounds__(256)
void attn_out(const float* __restrict__ qkv, const float* __restrict__ ctx,
              float* __restrict__ att)
{
    int n0 = blockIdx.x * 128, h = blockIdx.y, b = blockIdx.z;
    const float* qbase = qkv + ((size_t)b * O3 + h * DH) * (size_t)NPIX;
    const float* cbase = ctx + (size_t)(b * HEADS + h) * DH * DH;

    __shared__ float Cs[64][64];
    __shared__ float Qs[16][128];

    int t  = threadIdx.x;
    int ty = t >> 4, tx = t & 15;

    #pragma unroll
    for (int i = 0; i < 4; i++)
        ((float4*)Cs)[t + i * 256] = ((const float4*)cbase)[t + i * 256];

    float acc[4][8];
    #pragma unroll
    for (int i = 0; i < 4; i++)
        #pragma unroll
        for (int j = 0; j < 8; j++) acc[i][j] = 0.f;

    int qd = t >> 5;          // 0..7
    int qn = (t & 31) * 4;    // 0..124

    for (int d0 = 0; d0 < DH; d0 += 16) {
        __syncthreads();
        #pragma unroll
        for (int i = 0; i < 2; i++) {
            int dd = qd + i * 8;
            *(float4*)&Qs[dd][qn] =
                *(const float4*)(qbase + (size_t)(d0 + dd) * NPIX + n0 + qn);
        }
        __syncthreads();
        #pragma unroll
        for (int dd = 0; dd < 16; dd++) {
            int d = d0 + dd;
            float4 a  = *(float4*)&Cs[d][ty * 4];
            float4 b0 = *(float4*)&Qs[dd][tx * 8];
            float4 b1 = *(float4*)&Qs[dd][tx * 8 + 4];
            float av[4] = {a.x, a.y, a.z, a.w};
            float bv[8] = {b0.x, b0.y, b0.z, b0.w, b1.x, b1.y, b1.z, b1.w};
            #pragma unroll
            for (int i = 0; i < 4; i++)
                #pragma unroll
                for (int j = 0; j < 8; j++)
                    acc[i][j] = fmaf(av[i], bv[j], acc[i][j]);
        }
    }

    #pragma unroll
    for (int i = 0; i < 4; i++) {
        int e = ty * 4 + i;
        size_t off = ((size_t)b * CDIM + h * DH + e) * NPIX + n0 + tx * 8;
        float4 o0 = {acc[i][0], acc[i][1], acc[i][2], acc[i][3]};
        float4 o1 = {acc[i][4], acc[i][5], acc[i][6], acc[i][7]};
        *(float4*)(att + off)     = o0;
        *(float4*)(att + off + 4) = o1;
    }
}

// ============================================================================
// launch
// ============================================================================
extern "C" void kernel_launch(void* const* d_in, const int* in_sizes, int n_in,
                              void* d_out, int out_size)
{
    const float* x      = (const float*)d_in[0];
    const float* w_qkv  = (const float*)d_in[1];
    const float* w_out  = (const float*)d_in[2];
    const float* b_out  = (const float*)d_in[3];
    const float* gamma  = (const float*)d_in[4];
    float*       y      = (float*)d_out;

    void *pqkv, *pctxp, *pctx, *patt;
    cudaGetSymbolAddress(&pqkv,  g_qkv);
    cudaGetSymbolAddress(&pctxp, g_ctxp);
    cudaGetSymbolAddress(&pctx,  g_ctx);
    cudaGetSymbolAddress(&patt,  g_att);
    float* qkv  = (float*)pqkv;
    float* ctxp = (float*)pctxp;
    float* ctx  = (float*)pctx;
    float* att  = (float*)patt;

    // 1) QKV GEMM: qkv[b] = w_qkv[768,256] @ x[b][256,4096]
    gemm_tn<0><<<dim3(NPIX / 128, O3 / 128, BATCH), 256>>>(
        w_qkv, x, qkv, CDIM,
        (long)CDIM * NPIX, (long)O3 * NPIX,
        nullptr, nullptr, nullptr);

    // 2) softmax over n on K rows (in place)
    softmax_k<<<BATCH * 256, 256>>>(qkv);

    // 3) context = K @ V^T per (b,h), split over n + deterministic reduce
    ctx_partial<<<dim3(NSPLIT, HEADS, BATCH), 256>>>(qkv, ctxp);
    ctx_reduce<<<(BATCH * HEADS * DH * DH) / 256, 256>>>(ctxp, ctx);

    // 4) out = ctx^T @ Q per (b,h)
    attn_out<<<dim3(NPIX / 128, HEADS, BATCH), 256>>>(qkv, ctx, att);

    // 5) y = gamma * (w_out @ out + b_out) + x
    gemm_tn<1><<<dim3(NPIX / 128, CDIM / 128, BATCH), 256>>>(
        w_out, att, y, CDIM,
        (long)CDIM * NPIX, (long)CDIM * NPIX,
        b_out, gamma, x);
}

// round 4
// speedup vs baseline: 3.0561x; 3.0561x over previous
#include <cuda_runtime.h>
#include <cuda_bf16.h>
#include <cstdint>

#define BATCH 16
#define CDIM  256
#define NPIX  4096
#define O3    768
#define HEADS 4
#define DH    64
#define NSPL  8

// ------------------------- scratch ------------------------------------------
__device__ __nv_bfloat16 g_wb  [O3 * CDIM];                       // w_qkv bf16
__device__ __nv_bfloat16 g_xt  [(size_t)BATCH * NPIX * CDIM];     // x^T  [b][n][c]
__device__ __nv_bfloat16 g_qkvb[(size_t)BATCH * O3 * NPIX];       // qkv  [b][o][n]
__device__ __nv_bfloat16 g_qt  [(size_t)BATCH * NPIX * CDIM];     // q^T  [b][n][hd]
__device__ float         g_ctxp[BATCH * HEADS * NSPL * DH * DH];  // ctx partials
__device__ __nv_bfloat16 g_weff[BATCH * CDIM * CDIM];             // Weff [b][o][hd]

// ------------------------- mma helpers --------------------------------------
__device__ __forceinline__ uint32_t cvta_s(const void* p) {
    return (uint32_t)__cvta_generic_to_shared(p);
}
__device__ __forceinline__ void ldsm4(uint32_t* r, uint32_t a) {
    asm volatile("ldmatrix.sync.aligned.m8n8.x4.shared.b16 {%0,%1,%2,%3},[%4];"
                 : "=r"(r[0]), "=r"(r[1]), "=r"(r[2]), "=r"(r[3]) : "r"(a));
}
__device__ __forceinline__ void mma16816(float* d, const uint32_t* a, const uint32_t* b) {
    asm volatile(
        "mma.sync.aligned.m16n8k16.row.col.f32.bf16.bf16.f32 "
        "{%0,%1,%2,%3},{%4,%5,%6,%7},{%8,%9},{%0,%1,%2,%3};"
        : "+f"(d[0]), "+f"(d[1]), "+f"(d[2]), "+f"(d[3])
        : "r"(a[0]), "r"(a[1]), "r"(a[2]), "r"(a[3]), "r"(b[0]), "r"(b[1]));
}

// ============================================================================
// bf16 tensor-core GEMM: C[b][M][4096] = A[b][M][256] @ B[b][4096][256]^T
// Both operands K-major. 128x128 block tile, BK=32, 256 thr (8 warps 2x4),
// warp tile 64x32 (4x4 m16n8k16).
// EPI 0: bf16 out.  EPI 1: y = gamma[m]*(acc+bias[m]) + x  (fp32)
// ============================================================================
template <int EPI>
__global__ void __launch_bounds__(256)
gemm_mma(const __nv_bfloat16* __restrict__ A, long strideA,
         const __nv_bfloat16* __restrict__ B,
         float* __restrict__ outf, __nv_bfloat16* __restrict__ outb,
         long strideC,
         const float* __restrict__ bias, const float* __restrict__ gamma,
         const float* __restrict__ xres)
{
    __shared__ __nv_bfloat16 As[128][40];
    __shared__ __nv_bfloat16 Bs[128][40];

    const int t = threadIdx.x, lane = t & 31, w = t >> 5;
    const int wm = w >> 2, wn = w & 3;
    const int b = blockIdx.z, m0 = blockIdx.y * 128, n0 = blockIdx.x * 128;

    const __nv_bfloat16* Ab = A + (size_t)b * strideA;
    const __nv_bfloat16* Bb = B + (size_t)b * NPIX * CDIM;

    float acc[4][4][4];
    #pragma unroll
    for (int i = 0; i < 4; i++)
        #pragma unroll
        for (int j = 0; j < 4; j++)
            #pragma unroll
            for (int c = 0; c < 4; c++) acc[i][j][c] = 0.f;

    const int lr = t >> 2;          // 0..63
    const int lc = (t & 3) * 8;     // 0,8,16,24

    // ldmatrix source addresses (lane-dependent rows/cols)
    const int a_row = (lane & 7) + 8 * ((lane >> 3) & 1);
    const int a_kad = 8 * (lane >> 4);
    const int b_row = (lane & 7) + 8 * ((lane >> 4) & 1);
    const int b_kad = 8 * ((lane >> 3) & 1);

    for (int k0 = 0; k0 < CDIM; k0 += 32) {
        *(uint4*)&As[lr][lc]      = *(const uint4*)(Ab + (size_t)(m0 + lr) * CDIM + k0 + lc);
        *(uint4*)&As[lr + 64][lc] = *(const uint4*)(Ab + (size_t)(m0 + lr + 64) * CDIM + k0 + lc);
        *(uint4*)&Bs[lr][lc]      = *(const uint4*)(Bb + (size_t)(n0 + lr) * CDIM + k0 + lc);
        *(uint4*)&Bs[lr + 64][lc] = *(const uint4*)(Bb + (size_t)(n0 + lr + 64) * CDIM + k0 + lc);
        __syncthreads();

        #pragma unroll
        for (int ki = 0; ki < 32; ki += 16) {
            uint32_t af[4][4], bf[2][4];
            #pragma unroll
            for (int mi = 0; mi < 4; mi++)
                ldsm4(af[mi], cvta_s(&As[wm * 64 + mi * 16 + a_row][ki + a_kad]));
            #pragma unroll
            for (int n2 = 0; n2 < 2; n2++)
                ldsm4(bf[n2], cvta_s(&Bs[wn * 32 + n2 * 16 + b_row][ki + b_kad]));
            #pragma unroll
            for (int mi = 0; mi < 4; mi++)
                #pragma unroll
                for (int nj = 0; nj < 4; nj++)
                    mma16816(acc[mi][nj], af[mi], &bf[nj >> 1][(nj & 1) * 2]);
        }
        __syncthreads();
    }

    const int gid = lane >> 2, tig = lane & 3;
    #pragma unroll
    for (int mi = 0; mi < 4; mi++) {
        int m = m0 + wm * 64 + mi * 16 + gid;
        if (EPI == 0) {
            __nv_bfloat16* C0 = outb + (size_t)b * strideC + (size_t)m * NPIX;
            __nv_bfloat16* C1 = C0 + 8 * NPIX;
            #pragma unroll
            for (int nj = 0; nj < 4; nj++) {
                int n = n0 + wn * 32 + nj * 8 + tig * 2;
                __nv_bfloat162 lo = __floats2bfloat162_rn(acc[mi][nj][0], acc[mi][nj][1]);
                __nv_bfloat162 hi = __floats2bfloat162_rn(acc[mi][nj][2], acc[mi][nj][3]);
                *(__nv_bfloat162*)(C0 + n) = lo;
                *(__nv_bfloat162*)(C1 + n) = hi;
            }
        } else {
            float g0 = gamma[m], g1 = gamma[m + 8];
            float bo0 = bias[m], bo1 = bias[m + 8];
            float*       C0 = outf + (size_t)b * strideC + (size_t)m * NPIX;
            float*       C1 = C0 + 8 * NPIX;
            const float* X0 = xres + (size_t)b * strideC + (size_t)m * NPIX;
            const float* X1 = X0 + 8 * NPIX;
            #pragma unroll
            for (int nj = 0; nj < 4; nj++) {
                int n = n0 + wn * 32 + nj * 8 + tig * 2;
                float2 x0 = *(const float2*)(X0 + n);
                float2 x1 = *(const float2*)(X1 + n);
                float2 o0, o1;
                o0.x = fmaf(g0, acc[mi][nj][0] + bo0, x0.x);
                o0.y = fmaf(g0, acc[mi][nj][1] + bo0, x0.y);
                o1.x = fmaf(g1, acc[mi][nj][2] + bo1, x1.x);
                o1.y = fmaf(g1, acc[mi][nj][3] + bo1, x1.y);
                *(float2*)(C0 + n) = o0;
                *(float2*)(C1 + n) = o1;
            }
        }
    }
}

// ============================================================================
// ctx partial: ctxp[b,h,s][d][e] = sum_{n in split s} K[d,n] * V[e,n]
// M=N=64 (d,e), contraction over n (512 per split), BK=64.
// 128 threads (4 warps, 2x2), warp tile 32x32.
// ============================================================================
__global__ void __launch_bounds__(128)
ctx_mma(const __nv_bfloat16* __restrict__ qkv, float* __restrict__ ctxp)
{
    __shared__ __nv_bfloat16 Ks[64][72];
    __shared__ __nv_bfloat16 Vs[64][72];

    const int s = blockIdx.x, h = blockIdx.y, b = blockIdx.z;
    const int t = threadIdx.x, lane = t & 31, w = t >> 5;
    const int wm = w >> 1, wn = w & 1;

    const __nv_bfloat16* kb = qkv + ((size_t)b * O3 + 256 + h * DH) * NPIX + s * (NPIX / NSPL);
    const __nv_bfloat16* vb = qkv + ((size_t)b * O3 + 512 + h * DH) * NPIX + s * (NPIX / NSPL);

    float acc[2][4][4];
    #pragma unroll
    for (int i = 0; i < 2; i++)
        #pragma unroll
        for (int j = 0; j < 4; j++)
            #pragma unroll
            for (int c = 0; c < 4; c++) acc[i][j][c] = 0.f;

    const int a_row = (lane & 7) + 8 * ((lane >> 3) & 1);
    const int a_kad = 8 * (lane >> 4);
    const int b_row = (lane & 7) + 8 * ((lane >> 4) & 1);
    const int b_kad = 8 * ((lane >> 3) & 1);

    for (int k0 = 0; k0 < NPIX / NSPL; k0 += 64) {
        #pragma unroll
        for (int i = 0; i < 4; i++) {
            int u = i * 128 + t;                 // 0..511
            int row = u >> 3, col = (u & 7) * 8;
            *(uint4*)&Ks[row][col] = *(const uint4*)(kb + (size_t)row * NPIX + k0 + col);
            *(uint4*)&Vs[row][col] = *(const uint4*)(vb + (size_t)row * NPIX + k0 + col);
        }
        __syncthreads();

        #pragma unroll
        for (int ki = 0; ki < 64; ki += 16) {
            uint32_t af[2][4], bf[2][4];
            #pragma unroll
            for (int mi = 0; mi < 2; mi++)
                ldsm4(af[mi], cvta_s(&Ks[wm * 32 + mi * 16 + a_row][ki + a_kad]));
            #pragma unroll
            for (int n2 = 0; n2 < 2; n2++)
                ldsm4(bf[n2], cvta_s(&Vs[wn * 32 + n2 * 16 + b_row][ki + b_kad]));
            #pragma unroll
            for (int mi = 0; mi < 2; mi++)
                #pragma unroll
                for (int nj = 0; nj < 4; nj++)
                    mma16816(acc[mi][nj], af[mi], &bf[nj >> 1][(nj & 1) * 2]);
        }
        __syncthreads();
    }

    const int gid = lane >> 2, tig = lane & 3;
    float* dst = ctxp + (((size_t)(b * HEADS + h) * NSPL + s)) * (DH * DH);
    #pragma unroll
    for (int mi = 0; mi < 2; mi++) {
        int d = wm * 32 + mi * 16 + gid;
        #pragma unroll
        for (int nj = 0; nj < 4; nj++) {
            int e = wn * 32 + nj * 8 + tig * 2;
            *(float2*)(dst + (size_t)d * DH + e)       = make_float2(acc[mi][nj][0], acc[mi][nj][1]);
            *(float2*)(dst + (size_t)(d + 8) * DH + e) = make_float2(acc[mi][nj][2], acc[mi][nj][3]);
        }
    }
}

// ============================================================================
// small kernels
// ============================================================================
__global__ __launch_bounds__(256) void k_convw(const float* __restrict__ in,
                                               __nv_bfloat16* __restrict__ out) {
    int i = blockIdx.x * 256 + threadIdx.x;
    out[i] = __float2bfloat16(in[i]);
}

// x [b][256][4096] f32 -> xt [b][n][c] bf16
__global__ __launch_bounds__(256) void k_xt(const float* __restrict__ x,
                                            __nv_bfloat16* __restrict__ xt) {
    __shared__ __nv_bfloat16 ts[64][65];
    int n0 = blockIdx.x * 64, c0 = blockIdx.y * 64, b = blockIdx.z;
    int t = threadIdx.x;
    #pragma unroll
    for (int i = 0; i < 16; i++) {
        int idx = i * 256 + t, cc = idx >> 6, nn = idx & 63;
        ts[cc][nn] = __float2bfloat16(x[((size_t)b * CDIM + c0 + cc) * NPIX + n0 + nn]);
    }
    __syncthreads();
    #pragma unroll
    for (int i = 0; i < 16; i++) {
        int idx = i * 256 + t, nn = idx >> 6, cc = idx & 63;
        xt[((size_t)b * NPIX + n0 + nn) * CDIM + c0 + cc] = ts[cc][nn];
    }
}

// qkv rows 0..255 (q) bf16 -> qt [b][n][hd]
__global__ __launch_bounds__(256) void k_qt(const __nv_bfloat16* __restrict__ qkv,
                                            __nv_bfloat16* __restrict__ qt) {
    __shared__ __nv_bfloat16 ts[64][65];
    int n0 = blockIdx.x * 64, o0 = blockIdx.y * 64, b = blockIdx.z;
    int t = threadIdx.x;
    #pragma unroll
    for (int i = 0; i < 16; i++) {
        int idx = i * 256 + t, oo = idx >> 6, nn = idx & 63;
        ts[oo][nn] = qkv[((size_t)b * O3 + o0 + oo) * NPIX + n0 + nn];
    }
    __syncthreads();
    #pragma unroll
    for (int i = 0; i < 16; i++) {
        int idx = i * 256 + t, nn = idx >> 6, oo = idx & 63;
        qt[((size_t)b * NPIX + n0 + nn) * CDIM + o0 + oo] = ts[oo][nn];
    }
}

// softmax over n (4096) on K rows of qkv (bf16 in/out, fp32 math)
__global__ __launch_bounds__(256) void k_softmax(__nv_bfloat16* __restrict__ qkv) {
    int r = blockIdx.x, b = r >> 8, hd = r & 255;
    __nv_bfloat16* row = qkv + ((size_t)b * O3 + 256 + hd) * NPIX;
    uint4* row4 = (uint4*)row;
    int t = threadIdx.x;

    uint4 u0 = row4[t * 2], u1 = row4[t * 2 + 1];
    uint32_t wd[8] = { u0.x, u0.y, u0.z, u0.w, u1.x, u1.y, u1.z, u1.w };
    float f[16];
    #pragma unroll
    for (int i = 0; i < 8; i++) {
        __nv_bfloat162 h = *(__nv_bfloat162*)&wd[i];
        f[2 * i]     = __low2float(h);
        f[2 * i + 1] = __high2float(h);
    }

    float mx = -3.4e38f;
    #pragma unroll
    for (int i = 0; i < 16; i++) mx = fmaxf(mx, f[i]);

    __shared__ float sred[8];
    int lane = t & 31, wr = t >> 5;
    #pragma unroll
    for (int o = 16; o; o >>= 1) mx = fmaxf(mx, __shfl_xor_sync(~0u, mx, o));
    if (lane == 0) sred[wr] = mx;
    __syncthreads();
    if (t < 8) {
        float m2 = sred[t];
        #pragma unroll
        for (int o = 4; o; o >>= 1) m2 = fmaxf(m2, __shfl_xor_sync(0xffu, m2, o));
        if (t == 0) sred[0] = m2;
    }
    __syncthreads();
    mx = sred[0];
    __syncthreads();

    float sum = 0.f;
    #pragma unroll
    for (int i = 0; i < 16; i++) { f[i] = __expf(f[i] - mx); sum += f[i]; }
    #pragma unroll
    for (int o = 16; o; o >>= 1) sum += __shfl_xor_sync(~0u, sum, o);
    if (lane == 0) sred[wr] = sum;
    __syncthreads();
    if (t < 8) {
        float s2 = sred[t];
        #pragma unroll
        for (int o = 4; o; o >>= 1) s2 += __shfl_xor_sync(0xffu, s2, o);
        if (t == 0) sred[0] = s2;
    }
    __syncthreads();
    float inv = 1.0f / sred[0];

    #pragma unroll
    for (int i = 0; i < 8; i++) {
        __nv_bfloat162 h = __floats2bfloat162_rn(f[2 * i] * inv, f[2 * i + 1] * inv);
        wd[i] = *(uint32_t*)&h;
    }
    row4[t * 2]     = make_uint4(wd[0], wd[1], wd[2], wd[3]);
    row4[t * 2 + 1] = make_uint4(wd[4], wd[5], wd[6], wd[7]);
}

// Weff[b,o,h*64+d] = sum_e w_out[o,h*64+e] * ctx[b,h,d,e]  (ctx = sum partials)
__global__ __launch_bounds__(256) void k_weff(const float* __restrict__ ctxp,
                                              const float* __restrict__ w_out,
                                              __nv_bfloat16* __restrict__ weff) {
    __shared__ float cs[64][65];
    int bh = blockIdx.x, b = bh >> 2, h = bh & 3;
    int t = threadIdx.x;

    const float* cp = ctxp + ((size_t)bh * NSPL) * (DH * DH);
    #pragma unroll
    for (int i = 0; i < 16; i++) {
        int idx = i * 256 + t, d = idx >> 6, e = idx & 63;
        float v = 0.f;
        #pragma unroll
        for (int sp = 0; sp < NSPL; sp++) v += cp[(size_t)sp * (DH * DH) + idx];
        cs[d][e] = v;
    }
    __syncthreads();

    int o = t;
    float wrow[64];
    const float4* wp = (const float4*)(w_out + (size_t)o * CDIM + h * DH);
    #pragma unroll
    for (int i = 0; i < 16; i++) {
        float4 v = wp[i];
        wrow[i * 4] = v.x; wrow[i * 4 + 1] = v.y; wrow[i * 4 + 2] = v.z; wrow[i * 4 + 3] = v.w;
    }
    __nv_bfloat16* dst = weff + ((size_t)b * CDIM + o) * CDIM + h * DH;
    for (int d = 0; d < DH; d++) {
        float acc = 0.f;
        #pragma unroll 16
        for (int e = 0; e < DH; e++) acc = fmaf(wrow[e], cs[d][e], acc);
        dst[d] = __float2bfloat16(acc);
    }
}

// ============================================================================
// launch
// ============================================================================
extern "C" void kernel_launch(void* const* d_in, const int* in_sizes, int n_in,
                              void* d_out, int out_size)
{
    const float* x     = (const float*)d_in[0];
    const float* w_qkv = (const float*)d_in[1];
    const float* w_out = (const float*)d_in[2];
    const float* b_out = (const float*)d_in[3];
    const float* gamma = (const float*)d_in[4];
    float*       y     = (float*)d_out;

    void *pwb, *pxt, *pqkv, *pqt, *pctxp, *pweff;
    cudaGetSymbolAddress(&pwb,   g_wb);
    cudaGetSymbolAddress(&pxt,   g_xt);
    cudaGetSymbolAddress(&pqkv,  g_qkvb);
    cudaGetSymbolAddress(&pqt,   g_qt);
    cudaGetSymbolAddress(&pctxp, g_ctxp);
    cudaGetSymbolAddress(&pweff, g_weff);
    __nv_bfloat16* wb   = (__nv_bfloat16*)pwb;
    __nv_bfloat16* xt   = (__nv_bfloat16*)pxt;
    __nv_bfloat16* qkvb = (__nv_bfloat16*)pqkv;
    __nv_bfloat16* qt   = (__nv_bfloat16*)pqt;
    float*         ctxp = (float*)pctxp;
    __nv_bfloat16* weff = (__nv_bfloat16*)pweff;

    // 0) convert weights + transpose x
    k_convw<<<(O3 * CDIM) / 256, 256>>>(w_qkv, wb);
    k_xt<<<dim3(NPIX / 64, CDIM / 64, BATCH), 256>>>(x, xt);

    // 1) qkv = w_qkv @ x (bf16 HMMA)
    gemm_mma<0><<<dim3(NPIX / 128, O3 / 128, BATCH), 256>>>(
        wb, 0, xt, nullptr, qkvb, (long)O3 * NPIX, nullptr, nullptr, nullptr);

    // 2) softmax on K rows; q^T
    k_softmax<<<BATCH * 256, 256>>>(qkvb);
    k_qt<<<dim3(NPIX / 64, CDIM / 64, BATCH), 256>>>(qkvb, qt);

    // 3) ctx partials (8-way n-split) + Weff contraction
    ctx_mma<<<dim3(NSPL, HEADS, BATCH), 128>>>(qkvb, ctxp);
    k_weff<<<BATCH * HEADS, 256>>>(ctxp, w_out, weff);

    // 4) y = gamma*(Weff @ q + b_out) + x (bf16 HMMA + fused epilogue)
    gemm_mma<1><<<dim3(NPIX / 128, CDIM / 128, BATCH), 256>>>(
        weff, (long)CDIM * CDIM, qt, y, nullptr, (long)CDIM * NPIX,
        b_out, gamma, x);
}

// round 7
// speedup vs baseline: 3.6452x; 1.1928x over previous
#include <cuda_runtime.h>
#include <cuda_bf16.h>
#include <cstdint>

#define BATCH 16
#define CDIM  256
#define NPIX  4096
#define O3    768
#define HEADS 4
#define DH    64
#define NSPL  8

// ------------------------- scratch ------------------------------------------
__device__ __nv_bfloat16 g_wb  [O3 * CDIM];                       // w_qkv bf16
__device__ __nv_bfloat16 g_qkvb[(size_t)BATCH * O3 * NPIX];       // qkv  [b][o][n]
__device__ float         g_ctxp[BATCH * HEADS * NSPL * DH * DH];  // ctx partials
__device__ __nv_bfloat16 g_weff[BATCH * CDIM * CDIM];             // Weff [b][o][hd]

// ------------------------- mma helpers --------------------------------------
__device__ __forceinline__ uint32_t cvta_s(const void* p) {
    return (uint32_t)__cvta_generic_to_shared(p);
}
__device__ __forceinline__ void ldsm4(uint32_t* r, uint32_t a) {
    asm volatile("ldmatrix.sync.aligned.m8n8.x4.shared.b16 {%0,%1,%2,%3},[%4];"
                 : "=r"(r[0]), "=r"(r[1]), "=r"(r[2]), "=r"(r[3]) : "r"(a));
}
__device__ __forceinline__ void ldsm4t(uint32_t* r, uint32_t a) {
    asm volatile("ldmatrix.sync.aligned.m8n8.x4.trans.shared.b16 {%0,%1,%2,%3},[%4];"
                 : "=r"(r[0]), "=r"(r[1]), "=r"(r[2]), "=r"(r[3]) : "r"(a));
}
__device__ __forceinline__ void mma16816(float* d, const uint32_t* a, const uint32_t* b) {
    asm volatile(
        "mma.sync.aligned.m16n8k16.row.col.f32.bf16.bf16.f32 "
        "{%0,%1,%2,%3},{%4,%5,%6,%7},{%8,%9},{%0,%1,%2,%3};"
        : "+f"(d[0]), "+f"(d[1]), "+f"(d[2]), "+f"(d[3])
        : "r"(a[0]), "r"(a[1]), "r"(a[2]), "r"(a[3]), "r"(b[0]), "r"(b[1]));
}
__device__ __forceinline__ uint4 cvt8_bf16(float4 lo, float4 hi) {
    __nv_bfloat162 p0 = __floats2bfloat162_rn(lo.x, lo.y);
    __nv_bfloat162 p1 = __floats2bfloat162_rn(lo.z, lo.w);
    __nv_bfloat162 p2 = __floats2bfloat162_rn(hi.x, hi.y);
    __nv_bfloat162 p3 = __floats2bfloat162_rn(hi.z, hi.w);
    uint4 r;
    r.x = *(uint32_t*)&p0; r.y = *(uint32_t*)&p1;
    r.z = *(uint32_t*)&p2; r.w = *(uint32_t*)&p3;
    return r;
}

// ============================================================================
// bf16 HMMA GEMM:  C[b][M][4096] = A[b][M][256] @ B[b][256][4096]
//   A: [M][256] bf16 K-major.
//   B: NATURAL [K=256][N=4096] layout — bf16 (BF32=0) or f32 with on-the-fly
//      convert (BF32=1). Fragments via ldmatrix.x4.trans from XOR-swizzled smem.
//   128x128 block tile, BK=32, 256 thr (8 warps 2x4), warp tile 64x32.
//   Double-buffered smem, register prefetch, one sync per K-iter.
// EPI 0: bf16 out.  EPI 1: y = gamma[m]*(acc+bias[m]) + x  (fp32)
// ============================================================================
template <int EPI, int BF32>
__global__ void __launch_bounds__(256, 2)
gemm_mma(const __nv_bfloat16* __restrict__ A, long strideA,
         const __nv_bfloat16* __restrict__ Bb16, const float* __restrict__ Bf32,
         long strideB,
         float* __restrict__ outf, __nv_bfloat16* __restrict__ outb,
         long strideC,
         const float* __restrict__ bias, const float* __restrict__ gamma,
         const float* __restrict__ xres)
{
    __shared__ __nv_bfloat16 As[2][128][40];   // padded rows
    __shared__ __nv_bfloat16 Bs[2][32][128];   // XOR-swizzled (ngrp ^ (k&15))

    const int t = threadIdx.x, lane = t & 31, w = t >> 5;
    const int wm = w >> 2, wn = w & 3;
    const int b = blockIdx.z, m0 = blockIdx.y * 128, n0 = blockIdx.x * 128;

    const __nv_bfloat16* Ab = A + (size_t)b * strideA;
    const __nv_bfloat16* Bb = BF32 ? nullptr : (Bb16 + (size_t)b * strideB);
    const float*         Bf = BF32 ? (Bf32 + (size_t)b * strideB) : nullptr;

    float acc[4][4][4];
    #pragma unroll
    for (int i = 0; i < 4; i++)
        #pragma unroll
        for (int j = 0; j < 4; j++)
            #pragma unroll
            for (int c = 0; c < 4; c++) acc[i][j][c] = 0.f;

    // ---- staging coords ----
    const int am0 = t >> 2, akg = (t & 3) * 8;          // A rows 0..63 / +64
    const int bk0 = t >> 4, bng = t & 15;               // B rows 0..15 / +16
    const int bp0 = (bng ^ (bk0 & 15)) * 8;             // swizzled col (elems)
    const int bp1 = (bng ^ ((bk0 + 16) & 15)) * 8;

    // ---- fragment source addresses ----
    const int a_row = (lane & 7) + 8 * ((lane >> 3) & 1);
    const int a_kad = 8 * (lane >> 4);
    const int b_krow = lane & 15;                       // + ki
    const int b_nsub = lane >> 4;                       // 0/1 (8-col half)

    uint4 ra0, ra1, rb0, rb1;

    // prefetch tile 0
    ra0 = *(const uint4*)(Ab + (size_t)(m0 + am0) * CDIM + akg);
    ra1 = *(const uint4*)(Ab + (size_t)(m0 + am0 + 64) * CDIM + akg);
    if (BF32) {
        const float* r0 = Bf + (size_t)bk0 * NPIX + n0 + bng * 8;
        const float* r1 = Bf + (size_t)(bk0 + 16) * NPIX + n0 + bng * 8;
        rb0 = cvt8_bf16(*(const float4*)r0, *(const float4*)(r0 + 4));
        rb1 = cvt8_bf16(*(const float4*)r1, *(const float4*)(r1 + 4));
    } else {
        rb0 = *(const uint4*)(Bb + (size_t)bk0 * NPIX + n0 + bng * 8);
        rb1 = *(const uint4*)(Bb + (size_t)(bk0 + 16) * NPIX + n0 + bng * 8);
    }
    *(uint4*)&As[0][am0][akg]      = ra0;
    *(uint4*)&As[0][am0 + 64][akg] = ra1;
    *(uint4*)&Bs[0][bk0][bp0]      = rb0;
    *(uint4*)&Bs[0][bk0 + 16][bp1] = rb1;
    __syncthreads();

    const int KT = CDIM / 32;
    #pragma unroll 1
    for (int it = 0; it < KT; it++) {
        const int cur = it & 1, nxt = cur ^ 1;
        const int kN = (it + 1) * 32;
        if (it + 1 < KT) {
            ra0 = *(const uint4*)(Ab + (size_t)(m0 + am0) * CDIM + kN + akg);
            ra1 = *(const uint4*)(Ab + (size_t)(m0 + am0 + 64) * CDIM + kN + akg);
            if (BF32) {
                const float* r0 = Bf + (size_t)(kN + bk0) * NPIX + n0 + bng * 8;
                const float* r1 = Bf + (size_t)(kN + bk0 + 16) * NPIX + n0 + bng * 8;
                rb0 = cvt8_bf16(*(const float4*)r0, *(const float4*)(r0 + 4));
                rb1 = cvt8_bf16(*(const float4*)r1, *(const float4*)(r1 + 4));
            } else {
                rb0 = *(const uint4*)(Bb + (size_t)(kN + bk0) * NPIX + n0 + bng * 8);
                rb1 = *(const uint4*)(Bb + (size_t)(kN + bk0 + 16) * NPIX + n0 + bng * 8);
            }
        }

        #pragma unroll
        for (int ki = 0; ki < 32; ki += 16) {
            uint32_t af[4][4], bfr[2][4];
            #pragma unroll
            for (int mi = 0; mi < 4; mi++)
                ldsm4(af[mi], cvta_s(&As[cur][wm * 64 + mi * 16 + a_row][ki + a_kad]));
            #pragma unroll
            for (int n2 = 0; n2 < 2; n2++) {
                int krow = ki + b_krow;
                int glog = wn * 4 + n2 * 2 + b_nsub;
                int gphy = glog ^ (krow & 15);
                ldsm4t(bfr[n2], cvta_s(&Bs[cur][krow][gphy * 8]));
            }
            #pragma unroll
            for (int mi = 0; mi < 4; mi++)
                #pragma unroll
                for (int nj = 0; nj < 4; nj++)
                    mma16816(acc[mi][nj], af[mi], &bfr[nj >> 1][(nj & 1) * 2]);
        }

        if (it + 1 < KT) {
            *(uint4*)&As[nxt][am0][akg]      = ra0;
            *(uint4*)&As[nxt][am0 + 64][akg] = ra1;
            *(uint4*)&Bs[nxt][bk0][bp0]      = rb0;
            *(uint4*)&Bs[nxt][bk0 + 16][bp1] = rb1;
        }
        __syncthreads();
    }

    const int gid = lane >> 2, tig = lane & 3;
    #pragma unroll
    for (int mi = 0; mi < 4; mi++) {
        int m = m0 + wm * 64 + mi * 16 + gid;
        if (EPI == 0) {
            __nv_bfloat16* C0 = outb + (size_t)b * strideC + (size_t)m * NPIX;
            __nv_bfloat16* C1 = C0 + 8 * NPIX;
            #pragma unroll
            for (int nj = 0; nj < 4; nj++) {
                int n = n0 + wn * 32 + nj * 8 + tig * 2;
                __nv_bfloat162 lo = __floats2bfloat162_rn(acc[mi][nj][0], acc[mi][nj][1]);
                __nv_bfloat162 hi = __floats2bfloat162_rn(acc[mi][nj][2], acc[mi][nj][3]);
                *(__nv_bfloat162*)(C0 + n) = lo;
                *(__nv_bfloat162*)(C1 + n) = hi;
            }
        } else {
            const float g0 = gamma[m], g1 = gamma[m + 8];
            const float bo0 = bias[m], bo1 = bias[m + 8];
            float*       C0 = outf + (size_t)b * strideC + (size_t)m * NPIX;
            float*       C1 = C0 + 8 * NPIX;
            const float* X0 = xres + (size_t)b * strideC + (size_t)m * NPIX;
            const float* X1 = X0 + 8 * NPIX;
            #pragma unroll
            for (int nj = 0; nj < 4; nj++) {
                int n = n0 + wn * 32 + nj * 8 + tig * 2;
                float2 x0 = *(const float2*)(X0 + n);
                float2 x1 = *(const float2*)(X1 + n);
                float2 o0, o1;
                o0.x = fmaf(g0, acc[mi][nj][0] + bo0, x0.x);
                o0.y = fmaf(g0, acc[mi][nj][1] + bo0, x0.y);
                o1.x = fmaf(g1, acc[mi][nj][2] + bo1, x1.x);
                o1.y = fmaf(g1, acc[mi][nj][3] + bo1, x1.y);
                *(float2*)(C0 + n) = o0;
                *(float2*)(C1 + n) = o1;
            }
        }
    }
}

// ============================================================================
// ctx partial: ctxp[b,h,s][d][e] = sum_{n in split s} K[d,n] * V[e,n]
// ============================================================================
__global__ void __launch_bounds__(128)
ctx_mma(const __nv_bfloat16* __restrict__ qkv, float* __restrict__ ctxp)
{
    __shared__ __nv_bfloat16 Ks[64][72];
    __shared__ __nv_bfloat16 Vs[64][72];

    const int s = blockIdx.x, h = blockIdx.y, b = blockIdx.z;
    const int t = threadIdx.x, lane = t & 31, w = t >> 5;
    const int wm = w >> 1, wn = w & 1;

    const __nv_bfloat16* kb = qkv + ((size_t)b * O3 + 256 + h * DH) * NPIX + s * (NPIX / NSPL);
    const __nv_bfloat16* vb = qkv + ((size_t)b * O3 + 512 + h * DH) * NPIX + s * (NPIX / NSPL);

    float acc[2][4][4];
    #pragma unroll
    for (int i = 0; i < 2; i++)
        #pragma unroll
        for (int j = 0; j < 4; j++)
            #pragma unroll
            for (int c = 0; c < 4; c++) acc[i][j][c] = 0.f;

    const int a_row = (lane & 7) + 8 * ((lane >> 3) & 1);
    const int a_kad = 8 * (lane >> 4);
    const int b_row = (lane & 7) + 8 * ((lane >> 4) & 1);
    const int b_kad = 8 * ((lane >> 3) & 1);

    for (int k0 = 0; k0 < NPIX / NSPL; k0 += 64) {
        #pragma unroll
        for (int i = 0; i < 4; i++) {
            int u = i * 128 + t;
            int row = u >> 3, col = (u & 7) * 8;
            *(uint4*)&Ks[row][col] = *(const uint4*)(kb + (size_t)row * NPIX + k0 + col);
            *(uint4*)&Vs[row][col] = *(const uint4*)(vb + (size_t)row * NPIX + k0 + col);
        }
        __syncthreads();

        #pragma unroll
        for (int ki = 0; ki < 64; ki += 16) {
            uint32_t af[2][4], bfr[2][4];
            #pragma unroll
            for (int mi = 0; mi < 2; mi++)
                ldsm4(af[mi], cvta_s(&Ks[wm * 32 + mi * 16 + a_row][ki + a_kad]));
            #pragma unroll
            for (int n2 = 0; n2 < 2; n2++)
                ldsm4(bfr[n2], cvta_s(&Vs[wn * 32 + n2 * 16 + b_row][ki + b_kad]));
            #pragma unroll
            for (int mi = 0; mi < 2; mi++)
                #pragma unroll
                for (int nj = 0; nj < 4; nj++)
                    mma16816(acc[mi][nj], af[mi], &bfr[nj >> 1][(nj & 1) * 2]);
        }
        __syncthreads();
    }

    const int gid = lane >> 2, tig = lane & 3;
    float* dst = ctxp + (((size_t)(b * HEADS + h) * NSPL + s)) * (DH * DH);
    #pragma unroll
    for (int mi = 0; mi < 2; mi++) {
        int d = wm * 32 + mi * 16 + gid;
        #pragma unroll
        for (int nj = 0; nj < 4; nj++) {
            int e = wn * 32 + nj * 8 + tig * 2;
            *(float2*)(dst + (size_t)d * DH + e)       = make_float2(acc[mi][nj][0], acc[mi][nj][1]);
            *(float2*)(dst + (size_t)(d + 8) * DH + e) = make_float2(acc[mi][nj][2], acc[mi][nj][3]);
        }
    }
}

// ============================================================================
// small kernels
// ============================================================================
__global__ __launch_bounds__(256) void k_convw(const float* __restrict__ in,
                                               __nv_bfloat16* __restrict__ out) {
    int i = blockIdx.x * 256 + threadIdx.x;
    out[i] = __float2bfloat16(in[i]);
}

// softmax over n (4096) on K rows of qkv (bf16 in/out, fp32 math)
__global__ __launch_bounds__(256) void k_softmax(__nv_bfloat16* __restrict__ qkv) {
    int r = blockIdx.x, b = r >> 8, hd = r & 255;
    __nv_bfloat16* row = qkv + ((size_t)b * O3 + 256 + hd) * NPIX;
    uint4* row4 = (uint4*)row;
    int t = threadIdx.x;

    uint4 u0 = row4[t * 2], u1 = row4[t * 2 + 1];
    uint32_t wd[8] = { u0.x, u0.y, u0.z, u0.w, u1.x, u1.y, u1.z, u1.w };
    float f[16];
    #pragma unroll
    for (int i = 0; i < 8; i++) {
        __nv_bfloat162 h = *(__nv_bfloat162*)&wd[i];
        f[2 * i]     = __low2float(h);
        f[2 * i + 1] = __high2float(h);
    }

    float mx = -3.4e38f;
    #pragma unroll
    for (int i = 0; i < 16; i++) mx = fmaxf(mx, f[i]);

    __shared__ float sred[8];
    int lane = t & 31, wr = t >> 5;
    #pragma unroll
    for (int o = 16; o; o >>= 1) mx = fmaxf(mx, __shfl_xor_sync(~0u, mx, o));
    if (lane == 0) sred[wr] = mx;
    __syncthreads();
    if (t < 8) {
        float m2 = sred[t];
        #pragma unroll
        for (int o = 4; o; o >>= 1) m2 = fmaxf(m2, __shfl_xor_sync(0xffu, m2, o));
        if (t == 0) sred[0] = m2;
    }
    __syncthreads();
    mx = sred[0];
    __syncthreads();

    float sum = 0.f;
    #pragma unroll
    for (int i = 0; i < 16; i++) { f[i] = __expf(f[i] - mx); sum += f[i]; }
    #pragma unroll
    for (int o = 16; o; o >>= 1) sum += __shfl_xor_sync(~0u, sum, o);
    if (lane == 0) sred[wr] = sum;
    __syncthreads();
    if (t < 8) {
        float s2 = sred[t];
        #pragma unroll
        for (int o = 4; o; o >>= 1) s2 += __shfl_xor_sync(0xffu, s2, o);
        if (t == 0) sred[0] = s2;
    }
    __syncthreads();
    float inv = 1.0f / sred[0];

    #pragma unroll
    for (int i = 0; i < 8; i++) {
        __nv_bfloat162 h = __floats2bfloat162_rn(f[2 * i] * inv, f[2 * i + 1] * inv);
        wd[i] = *(uint32_t*)&h;
    }
    row4[t * 2]     = make_uint4(wd[0], wd[1], wd[2], wd[3]);
    row4[t * 2 + 1] = make_uint4(wd[4], wd[5], wd[6], wd[7]);
}

// Weff[b,o,h*64+d] = sum_e w_out[o,h*64+e] * ctx[b,h,d,e]  (ctx = sum partials)
__global__ __launch_bounds__(256) void k_weff(const float* __restrict__ ctxp,
                                              const float* __restrict__ w_out,
                                              __nv_bfloat16* __restrict__ weff) {
    __shared__ float cs[64][65];
    int bh = blockIdx.x, b = bh >> 2, h = bh & 3;
    int t = threadIdx.x;

    const float* cp = ctxp + ((size_t)bh * NSPL) * (DH * DH);
    #pragma unroll
    for (int i = 0; i < 16; i++) {
        int idx = i * 256 + t, d = idx >> 6, e = idx & 63;
        float v = 0.f;
        #pragma unroll
        for (int sp = 0; sp < NSPL; sp++) v += cp[(size_t)sp * (DH * DH) + idx];
        cs[d][e] = v;
    }
    __syncthreads();

    int o = t;
    float wrow[64];
    const float4* wp = (const float4*)(w_out + (size_t)o * CDIM + h * DH);
    #pragma unroll
    for (int i = 0; i < 16; i++) {
        float4 v = wp[i];
        wrow[i * 4] = v.x; wrow[i * 4 + 1] = v.y; wrow[i * 4 + 2] = v.z; wrow[i * 4 + 3] = v.w;
    }
    __nv_bfloat16* dst = weff + ((size_t)b * CDIM + o) * CDIM + h * DH;
    for (int d = 0; d < DH; d++) {
        float acc = 0.f;
        #pragma unroll 16
        for (int e = 0; e < DH; e++) acc = fmaf(wrow[e], cs[d][e], acc);
        dst[d] = __float2bfloat16(acc);
    }
}

// ============================================================================
// launch
// ============================================================================
extern "C" void kernel_launch(void* const* d_in, const int* in_sizes, int n_in,
                              void* d_out, int out_size)
{
    const float* x     = (const float*)d_in[0];
    const float* w_qkv = (const float*)d_in[1];
    const float* w_out = (const float*)d_in[2];
    const float* b_out = (const float*)d_in[3];
    const float* gamma = (const float*)d_in[4];
    float*       y     = (float*)d_out;

    void *pwb, *pqkv, *pctxp, *pweff;
    cudaGetSymbolAddress(&pwb,   g_wb);
    cudaGetSymbolAddress(&pqkv,  g_qkvb);
    cudaGetSymbolAddress(&pctxp, g_ctxp);
    cudaGetSymbolAddress(&pweff, g_weff);
    __nv_bfloat16* wb   = (__nv_bfloat16*)pwb;
    __nv_bfloat16* qkvb = (__nv_bfloat16*)pqkv;
    float*         ctxp = (float*)pctxp;
    __nv_bfloat16* weff = (__nv_bfloat16*)pweff;

    // 0) convert weights to bf16
    k_convw<<<(O3 * CDIM) / 256, 256>>>(w_qkv, wb);

    // 1) qkv = w_qkv @ x   (B = x f32, natural layout, fused convert)
    gemm_mma<0, 1><<<dim3(NPIX / 128, O3 / 128, BATCH), 256>>>(
        wb, 0, nullptr, x, (long)CDIM * NPIX,
        nullptr, qkvb, (long)O3 * NPIX, nullptr, nullptr, nullptr);

    // 2) softmax on K rows
    k_softmax<<<BATCH * 256, 256>>>(qkvb);

    // 3) ctx partials + Weff contraction
    ctx_mma<<<dim3(NSPL, HEADS, BATCH), 128>>>(qkvb, ctxp);
    k_weff<<<BATCH * HEADS, 256>>>(ctxp, w_out, weff);

    // 4) y = gamma*(Weff @ q + b_out) + x   (B = q rows of qkv, natural layout)
    gemm_mma<1, 0><<<dim3(NPIX / 128, CDIM / 128, BATCH), 256>>>(
        weff, (long)CDIM * CDIM, qkvb, nullptr, (long)O3 * NPIX,
        y, nullptr, (long)CDIM * NPIX, b_out, gamma, x);
}